// round 14
// baseline (speedup 1.0000x reference)
#include <cuda_runtime.h>
#include <cuda_fp16.h>
#include <cstdint>

#define NB 4
#define NC 256
#define NN 4096
#define TI 128
#define TJ 64
#define NSTEPS (NN / TJ)
#define TJ1 256
#define NSTEPS1 (NN / TJ1)

// ---------------- device scratch (allocation-free) ----------------
__device__ unsigned short g_q[(size_t)NB * NN * 64];     // [b][n][32hi|32lo] fp16
__device__ unsigned short g_k[(size_t)NB * NN * 64];
__device__ unsigned short g_v[(size_t)NB * NN * 256];    // [b][n][c] fp16
__device__ unsigned short g_xh[(size_t)NB * NC * NN];    // x hi plane [b][c][n]
__device__ unsigned short g_xl[(size_t)NB * NC * NN];    // x lo plane
__device__ unsigned short g_wvh[256 * 256];              // Wv hi [c][k]
__device__ unsigned short g_wvl[256 * 256];
__device__ unsigned short g_wqkh[64 * 256];              // Wq(0-31)|Wk(32-63) hi [c][k]
__device__ unsigned short g_wqkl[64 * 256];

// ---------------- attn SMEM layout (bytes) ----------------
#define SQ 0                       // 128 rows x 128B = 16384
#define SK 16384                   // + bf*8192 (64 rows x 128B)
#define SV 32768                   // + bf*32768 ; 64 j-rows x 512B
#define SPS 98304                  // P exchange: 128 rows x 128B = 16384
#define SL  114688                 // l sums: 128 floats
#define SMEMB 115200

// ---------------- proj SMEM ----------------
#define PJX 0          // x tile: [2 buf][32 k][512B: 128n hi | 128n lo]
#define PJW 32768      // W tile: [2 buf][<=128 c][128B: 32k hi | 32k lo]
#define PJ_SMEM 65536

// ---------------- PTX helpers ----------------
__device__ __forceinline__ uint32_t smem_u32(const void* p) {
    uint32_t a;
    asm("{ .reg .u64 t; cvta.to.shared.u64 t, %1; cvt.u32.u64 %0, t; }" : "=r"(a) : "l"(p));
    return a;
}
__device__ __forceinline__ void cp16(uint32_t dst, const void* src) {
    asm volatile("cp.async.cg.shared.global [%0], [%1], 16;" :: "r"(dst), "l"(src));
}
__device__ __forceinline__ void cp_commit() { asm volatile("cp.async.commit_group;" ::: "memory"); }
__device__ __forceinline__ void cp_wait0()  { asm volatile("cp.async.wait_group 0;" ::: "memory"); }

__device__ __forceinline__ void ldsm4(uint32_t* r, uint32_t a) {
    asm volatile("ldmatrix.sync.aligned.m8n8.x4.shared.b16 {%0,%1,%2,%3}, [%4];"
        : "=r"(r[0]), "=r"(r[1]), "=r"(r[2]), "=r"(r[3]) : "r"(a));
}
__device__ __forceinline__ void ldsm4t(uint32_t* r, uint32_t a) {
    asm volatile("ldmatrix.sync.aligned.m8n8.x4.trans.shared.b16 {%0,%1,%2,%3}, [%4];"
        : "=r"(r[0]), "=r"(r[1]), "=r"(r[2]), "=r"(r[3]) : "r"(a));
}
__device__ __forceinline__ void mma16816(float* d, const uint32_t* a, uint32_t b0, uint32_t b1) {
    asm volatile("mma.sync.aligned.m16n8k16.row.col.f32.f16.f16.f32 "
        "{%0,%1,%2,%3}, {%4,%5,%6,%7}, {%8,%9}, {%0,%1,%2,%3};"
        : "+f"(d[0]), "+f"(d[1]), "+f"(d[2]), "+f"(d[3])
        : "r"(a[0]), "r"(a[1]), "r"(a[2]), "r"(a[3]), "r"(b0), "r"(b1));
}
// pack: first arg -> low half, second -> high half
__device__ __forceinline__ uint32_t packh(float lo, float hi) {
    uint32_t r;
    asm("cvt.rn.f16x2.f32 %0, %1, %2;" : "=r"(r) : "f"(hi), "f"(lo));
    return r;
}
__device__ __forceinline__ unsigned short f16h(float v) {
    __half h = __float2half_rn(v);
    return *reinterpret_cast<unsigned short*>(&h);
}
__device__ __forceinline__ float f16f(unsigned short u) {
    __half h = *reinterpret_cast<__half*>(&u);
    return __half2float(h);
}
__device__ __forceinline__ uint32_t swz512(int ch, int row) {
    return (uint32_t)(((ch & 24) | ((ch ^ (row & 7)) & 7)) << 4);
}
__device__ __forceinline__ void cvt4(float4 v, uint2& hh, uint2& ll) {
    uint32_t h0 = packh(v.x, v.y), h1 = packh(v.z, v.w);
    float r0 = f16f((unsigned short)(h0 & 0xffffu));
    float r1 = f16f((unsigned short)(h0 >> 16));
    float r2 = f16f((unsigned short)(h1 & 0xffffu));
    float r3 = f16f((unsigned short)(h1 >> 16));
    hh = make_uint2(h0, h1);
    ll = make_uint2(packh(v.x - r0, v.y - r1), packh(v.z - r2, v.w - r3));
}

// ---------------- attn prefetchers (256 threads) ----------------
__device__ __forceinline__ void prefetch_k256(uint32_t sb, int bf, int b, int j0, int t) {
    #pragma unroll
    for (int kk = 0; kk < 4; kk++) {
        int idx = t + kk * 256;
        int row = idx >> 2, ch = idx & 3;
        cp16(sb + SV + bf * 16384 + row * 64 + ((ch ^ ((row >> 1) & 3)) << 4),
             g_k + ((size_t)(b * NN + j0 + row)) * 64 + ch * 8);
    }
}
__device__ __forceinline__ void prefetch_kv(uint32_t sb, int bf, int b, int j0, int t) {
    const unsigned short* ks = g_k + ((size_t)(b * NN + j0)) * 64;
    #pragma unroll
    for (int kk = 0; kk < 2; kk++) {
        int idx = t + kk * 256;
        int row = idx >> 3, ch = idx & 7;
        cp16(sb + SK + bf * 8192 + row * 128 + ((ch ^ (row & 7)) << 4),
             ks + (size_t)row * 64 + ch * 8);
    }
    const unsigned short* hs = g_v + ((size_t)(b * NN + j0)) * 256;
    #pragma unroll
    for (int kk = 0; kk < 8; kk++) {
        int idx = t + kk * 256;
        int row = idx >> 5, ch = idx & 31;
        uint32_t off = row * 512 + (((ch & 24) | ((ch ^ row) & 7)) << 4);
        cp16(sb + SV + bf * 32768 + off, hs + (size_t)row * 256 + ch * 8);
    }
}

// =====================================================================
// fp16 mma.sync flash attention; QK per 16-row warp (validated),
// PV c-split: warp (wi,wc) owns rows wi*32..+31 x c wc*128..+127,
// P exchanged through 16KB swizzled smem buffer.
// =====================================================================
__global__ __launch_bounds__(256, 1) void attn_kernel(
    const float* __restrict__ x, float* __restrict__ out)
{
    extern __shared__ char smem[];
    const uint32_t sb = smem_u32(smem);
    const int t = threadIdx.x, lane = t & 31, w = t >> 5;
    const int wi = w & 3, wc = w >> 2;
    const int b = blockIdx.y, i0 = blockIdx.x * TI;
    const int rr = lane >> 2, qd = lane & 3;
    const int l7 = lane & 7, lm8 = ((lane >> 3) & 1) * 8, lhi = lane >> 4, lm4 = lane >> 3;

    {
        const unsigned short* qs = g_q + ((size_t)(b * NN + i0)) * 64;
        #pragma unroll
        for (int kk = 0; kk < 4; kk++) {
            int idx = t + kk * 256;
            int row = idx >> 3, ch = idx & 7;
            cp16(sb + SQ + row * 128 + ((ch ^ (row & 7)) << 4),
                 qs + (size_t)row * 64 + ch * 8);
        }
        prefetch_k256(sb, 0, b, 0, t);
        cp_commit();
    }
    cp_wait0();
    __syncthreads();

    uint32_t qh[2][4], ql[2][4];
    #pragma unroll
    for (int kc = 0; kc < 2; kc++) {
        int row = w * 16 + l7 + lm8;
        int chh = 2 * kc + lhi;
        ldsm4(qh[kc], sb + SQ + row * 128 + ((chh ^ (row & 7)) << 4));
        ldsm4(ql[kc], sb + SQ + row * 128 + (((chh + 4) ^ (row & 7)) << 4));
    }

    // ---- PHASE 1: row max ----
    float mx0 = -1e30f, mx1 = -1e30f;
    for (int it = 0; it < NSTEPS1; it++) {
        const int bf = it & 1;
        if (it > 0) { cp_wait0(); __syncthreads(); }
        if (it + 1 < NSTEPS1) { prefetch_k256(sb, bf ^ 1, b, (it + 1) * TJ1, t); cp_commit(); }
        const uint32_t kb = sb + SV + bf * 16384;
        #pragma unroll
        for (int hb = 0; hb < 32; hb++) {
            float S[4] = {0.f, 0.f, 0.f, 0.f};
            int krow = hb * 8 + l7;
            uint32_t a = kb + krow * 64 + ((lm4 ^ ((krow >> 1) & 3)) << 4);
            uint32_t kh4[4];
            ldsm4(kh4, a);
            mma16816(S, qh[0], kh4[0], kh4[1]);
            mma16816(S, qh[1], kh4[2], kh4[3]);
            mx0 = fmaxf(mx0, fmaxf(S[0], S[1]));
            mx1 = fmaxf(mx1, fmaxf(S[2], S[3]));
        }
    }
    mx0 = fmaxf(mx0, __shfl_xor_sync(0xffffffffu, mx0, 1));
    mx0 = fmaxf(mx0, __shfl_xor_sync(0xffffffffu, mx0, 2));
    mx1 = fmaxf(mx1, __shfl_xor_sync(0xffffffffu, mx1, 1));
    mx1 = fmaxf(mx1, __shfl_xor_sync(0xffffffffu, mx1, 2));

    // ---- PHASE 2 ----
    float O[2][16][4];
    #pragma unroll
    for (int mi = 0; mi < 2; mi++)
        #pragma unroll
        for (int i = 0; i < 16; i++)
            #pragma unroll
            for (int j = 0; j < 4; j++) O[mi][i][j] = 0.f;
    float rs0 = 0.f, rs1 = 0.f;

    __syncthreads();
    prefetch_kv(sb, 0, b, 0, t);
    cp_commit();
    cp_wait0();
    __syncthreads();

    const int qrow0 = w * 16 + rr;           // QK-phase row (this warp's S rows)
    for (int st = 0; st < NSTEPS; st++) {
        const int bf = st & 1;
        if (st > 0) { cp_wait0(); __syncthreads(); }
        if (st + 1 < NSTEPS) { prefetch_kv(sb, bf ^ 1, b, (st + 1) * TJ, t); cp_commit(); }

        const uint32_t kbase = sb + SK + bf * 8192;
        const uint32_t vbase = sb + SV + bf * 32768;

        // ---- QK + exp + P store (rows w*16..+15, all 64 j) ----
        #pragma unroll
        for (int kc = 0; kc < 4; kc++) {
            float S[2][4];
            #pragma unroll
            for (int h = 0; h < 2; h++) {
                S[h][0] = S[h][1] = S[h][2] = S[h][3] = 0.f;
                int krow = (2 * kc + h) * 8 + l7;
                int swk = (krow & 7);
                uint32_t kh4[4], kl4[4];
                ldsm4(kh4, kbase + krow * 128 + ((lm4 ^ swk) << 4));
                ldsm4(kl4, kbase + krow * 128 + (((lm4 + 4) ^ swk) << 4));
                mma16816(S[h], qh[0], kh4[0], kh4[1]);
                mma16816(S[h], qh[1], kh4[2], kh4[3]);
                mma16816(S[h], qh[0], kl4[0], kl4[1]);
                mma16816(S[h], qh[1], kl4[2], kl4[3]);
                mma16816(S[h], ql[0], kh4[0], kh4[1]);
                mma16816(S[h], ql[1], kh4[2], kh4[3]);
            }
            #pragma unroll
            for (int h = 0; h < 2; h++) {
                float e0 = __expf(S[h][0] - mx0), e1 = __expf(S[h][1] - mx0);
                float e2 = __expf(S[h][2] - mx1), e3 = __expf(S[h][3] - mx1);
                rs0 += e0 + e1;
                rs1 += e2 + e3;
                int ch = 2 * kc + h;
                int r0 = qrow0, r1 = qrow0 + 8;
                *(uint32_t*)(smem + SPS + r0 * 128 + ((ch ^ (r0 & 7)) << 4) + qd * 4)
                    = packh(e0, e1);
                *(uint32_t*)(smem + SPS + r1 * 128 + ((ch ^ (r1 & 7)) << 4) + qd * 4)
                    = packh(e2, e3);
            }
        }
        __syncthreads();

        // ---- PV: rows wi*32..+31, c wc*128..+127 ----
        #pragma unroll
        for (int kc = 0; kc < 4; kc++) {
            uint32_t pf[2][4];
            #pragma unroll
            for (int mi = 0; mi < 2; mi++) {
                int prow = wi * 32 + mi * 16 + l7 + lm8;
                int ch = kc * 2 + lhi;
                ldsm4(pf[mi], sb + SPS + prow * 128 + ((ch ^ (prow & 7)) << 4));
            }
            int vrow = kc * 16 + l7 + lm8;
            uint32_t vroff = vbase + vrow * 512;
            int swv = (vrow & 7);
            #pragma unroll
            for (int vb = 0; vb < 8; vb++) {
                int ch = wc * 16 + vb * 2 + lhi;
                uint32_t a = vroff + ((((ch & 24) | ((ch ^ swv) & 7))) << 4);
                uint32_t v4[4];
                ldsm4t(v4, a);
                mma16816(O[0][2 * vb],     pf[0], v4[0], v4[1]);
                mma16816(O[0][2 * vb + 1], pf[0], v4[2], v4[3]);
                mma16816(O[1][2 * vb],     pf[1], v4[0], v4[1]);
                mma16816(O[1][2 * vb + 1], pf[1], v4[2], v4[3]);
            }
        }
    }

    // ---- l sums -> smem (QK row mapping), then epilogue (PV mapping) ----
    rs0 += __shfl_xor_sync(0xffffffffu, rs0, 1);
    rs0 += __shfl_xor_sync(0xffffffffu, rs0, 2);
    rs1 += __shfl_xor_sync(0xffffffffu, rs1, 1);
    rs1 += __shfl_xor_sync(0xffffffffu, rs1, 2);
    float* lsum = (float*)(smem + SL);
    __syncthreads();
    if (qd == 0) {
        lsum[qrow0] = rs0;
        lsum[qrow0 + 8] = rs1;
    }
    __syncthreads();

    #pragma unroll
    for (int mi = 0; mi < 2; mi++) {
        const int rloc = wi * 32 + mi * 16 + rr;
        const int ng = i0 + rloc;
        const float li0 = 1.0f / lsum[rloc];
        const float li1 = 1.0f / lsum[rloc + 8];
        #pragma unroll
        for (int cb = 0; cb < 16; cb++) {
            int c = wc * 128 + cb * 8 + qd * 2;
            size_t g = ((size_t)b * NC + c) * NN + ng;
            out[g]          = O[mi][cb][0] * li0 + x[g];
            out[g + NN]     = O[mi][cb][1] * li0 + x[g + NN];
            out[g + 8]      = O[mi][cb][2] * li1 + x[g + 8];
            out[g + 8 + NN] = O[mi][cb][3] * li1 + x[g + 8 + NN];
        }
    }
}

// =====================================================================
// convert: x -> fp16 hi/lo planes (blocks 0-1023, 4 f4/thread);
// Wv -> blocks 1024-1039; Wq -> 1040-1041; Wk -> 1042-1043.
// =====================================================================
__global__ __launch_bounds__(256) void convert_kernel(
    const float* __restrict__ x,
    const float* __restrict__ Wq, const float* __restrict__ Wk,
    const float* __restrict__ Wv)
{
    const int t = threadIdx.x;
    const int bx = blockIdx.x;
    if (bx < 1024) {
        const float4* xs = (const float4*)x;
        uint2* xh2 = (uint2*)g_xh;
        uint2* xl2 = (uint2*)g_xl;
        float4 v[4];
        size_t base = (size_t)bx * 1024 + t;
        #pragma unroll
        for (int kk = 0; kk < 4; kk++) v[kk] = xs[base + kk * 256];
        #pragma unroll
        for (int kk = 0; kk < 4; kk++) {
            uint2 hh, ll;
            cvt4(v[kk], hh, ll);
            xh2[base + kk * 256] = hh;
            xl2[base + kk * 256] = ll;
        }
    } else if (bx < 1040) {
        const float4* wv4 = (const float4*)Wv;
        uint2* vh2 = (uint2*)g_wvh;
        uint2* vl2 = (uint2*)g_wvl;
        float4 v[4];
        int base = (bx - 1024) * 1024 + t;
        #pragma unroll
        for (int kk = 0; kk < 4; kk++) v[kk] = wv4[base + kk * 256];
        #pragma unroll
        for (int kk = 0; kk < 4; kk++) {
            uint2 hh, ll;
            cvt4(v[kk], hh, ll);
            vh2[base + kk * 256] = hh;
            vl2[base + kk * 256] = ll;
        }
    } else {
        const bool isQ = bx < 1042;
        const float4* w4 = (const float4*)(isQ ? Wq : Wk);
        int base = ((bx - (isQ ? 1040 : 1042)) & 1) * 1024 + t;
        int off = isQ ? 0 : 2048;
        uint2* h2 = (uint2*)g_wqkh;
        uint2* l2 = (uint2*)g_wqkl;
        float4 v[4];
        #pragma unroll
        for (int kk = 0; kk < 4; kk++) v[kk] = w4[base + kk * 256];
        #pragma unroll
        for (int kk = 0; kk < 4; kk++) {
            uint2 hh, ll;
            cvt4(v[kk], hh, ll);
            h2[off + base + kk * 256] = hh;
            l2[off + base + kk * 256] = ll;
        }
    }
}

// =====================================================================
// proj v2: pure fp16 pipelined GEMM, D[n][c] = x^T W^T (3-product hi/lo)
// =====================================================================
template<int NU, bool ISV>
__device__ __forceinline__ void proj_body(
    char* ps, uint32_t sb, int b, int n0, int c0,
    const float* __restrict__ bq, const float* __restrict__ bk,
    const float* __restrict__ bv)
{
    const int t = threadIdx.x, lane = t & 31, w = t >> 5;
    const int rr = lane >> 2, qd = lane & 3;
    const int l7 = lane & 7, lhi = lane >> 4, lm4 = lane >> 3, lq = (lane >> 3) & 1;
    const unsigned short* wh_g = ISV ? g_wvh : g_wqkh;
    const unsigned short* wl_g = ISV ? g_wvl : g_wqkl;

    auto prefetch = [&](int bf, int k0) {
        #pragma unroll
        for (int kk = 0; kk < 4; kk++) {
            int idx = t + kk * 256;
            int row = idx >> 5, ch = idx & 31;
            const unsigned short* src = (ch < 16 ? g_xh : g_xl)
                + ((size_t)(b * NC + k0 + row)) * NN + n0 + (ch & 15) * 8;
            cp16(sb + PJX + bf * 16384 + row * 512 + swz512(ch, row), src);
        }
        #pragma unroll
        for (int kk = 0; kk < (ISV ? 4 : 2); kk++) {
            int idx = t + kk * 256;
            int row = idx >> 3, ch = idx & 7;
            const unsigned short* src = (ch < 4 ? wh_g : wl_g)
                + (size_t)(c0 + row) * 256 + k0 + (ch & 3) * 8;
            cp16(sb + PJW + bf * 16384 + row * 128 + ((ch ^ (row & 7)) << 4), src);
        }
    };

    float O[NU][4];
    #pragma unroll
    for (int i = 0; i < NU; i++)
        #pragma unroll
        for (int j = 0; j < 4; j++) O[i][j] = 0.f;

    prefetch(0, 0);
    cp_commit();

    for (int it = 0; it < 8; it++) {
        const int buf = it & 1;
        cp_wait0();
        __syncthreads();
        if (it < 7) { prefetch(buf ^ 1, (it + 1) * 32); cp_commit(); }

        uint32_t ah[2][4], al[2][4];
        #pragma unroll
        for (int kc = 0; kc < 2; kc++) {
            int krow = kc * 16 + l7 + lhi * 8;
            int chA = 2 * w + lq;
            uint32_t base = sb + PJX + buf * 16384 + krow * 512;
            ldsm4t(ah[kc], base + swz512(chA, krow));
            ldsm4t(al[kc], base + swz512(chA + 16, krow));
        }
        #pragma unroll
        for (int u = 0; u < NU; u++) {
            int crow = u * 8 + l7;
            uint32_t wb = sb + PJW + buf * 16384 + crow * 128;
            int sw = crow & 7;
            uint32_t whf[4], wlf[4];
            ldsm4(whf, wb + ((lm4 ^ sw) << 4));
            ldsm4(wlf, wb + (((lm4 + 4) ^ sw) << 4));
            mma16816(O[u], ah[0], whf[0], whf[1]);
            mma16816(O[u], ah[1], whf[2], whf[3]);
            mma16816(O[u], al[0], whf[0], whf[1]);
            mma16816(O[u], al[1], whf[2], whf[3]);
            mma16816(O[u], ah[0], wlf[0], wlf[1]);
            mma16816(O[u], ah[1], wlf[2], wlf[3]);
        }
    }

    const int n_lo = n0 + w * 16 + rr;
    if (ISV) {
        #pragma unroll
        for (int u = 0; u < NU; u++) {
            int c = c0 + u * 8 + qd * 2;
            float b0 = bv[c], b1 = bv[c + 1];
            uint32_t p0 = packh(O[u][0] + b0, O[u][1] + b1);
            uint32_t p1 = packh(O[u][2] + b0, O[u][3] + b1);
            *(uint32_t*)&g_v[((size_t)(b * NN + n_lo)) * 256 + c] = p0;
            *(uint32_t*)&g_v[((size_t)(b * NN + n_lo + 8)) * 256 + c] = p1;
        }
    } else {
        #pragma unroll
        for (int u = 0; u < NU; u++) {
            int c = u * 8 + qd * 2;
            bool isq = (c < 32);
            unsigned short* tgt = isq ? g_q : g_k;
            int cl = isq ? c : c - 32;
            const float* bb = isq ? bq : bk;
            float b0 = bb[cl], b1 = bb[cl + 1];
            #pragma unroll
            for (int hh = 0; hh < 2; hh++) {
                float v0 = O[u][2 * hh] + b0, v1 = O[u][2 * hh + 1] + b1;
                unsigned short h0 = f16h(v0), h1 = f16h(v1);
                uint32_t hp = ((uint32_t)h1 << 16) | h0;
                uint32_t lp = packh(v0 - f16f(h0), v1 - f16f(h1));
                size_t base = ((size_t)(b * NN + n_lo + hh * 8)) * 64;
                *(uint32_t*)&tgt[base + cl] = hp;
                *(uint32_t*)&tgt[base + 32 + cl] = lp;
            }
        }
    }
}

__global__ __launch_bounds__(256, 2) void proj_mma(
    const float* __restrict__ bq, const float* __restrict__ bk,
    const float* __restrict__ bv)
{
    extern __shared__ char ps[];
    const uint32_t sb = smem_u32(ps);
    const int b = blockIdx.z;
    if (blockIdx.x < 64) {
        proj_body<16, true>(ps, sb, b, (blockIdx.x >> 1) * 128,
                            (blockIdx.x & 1) * 128, bq, bk, bv);
    } else {
        proj_body<8, false>(ps, sb, b, ((int)blockIdx.x - 64) * 128, 0, bq, bk, bv);
    }
}

// =====================================================================
extern "C" void kernel_launch(void* const* d_in, const int* in_sizes, int n_in,
                              void* d_out, int out_size)
{
    const float* x  = (const float*)d_in[0];
    const float* Wq = (const float*)d_in[1];
    const float* bq = (const float*)d_in[2];
    const float* Wk = (const float*)d_in[3];
    const float* bk = (const float*)d_in[4];
    const float* Wv = (const float*)d_in[5];
    const float* bv = (const float*)d_in[6];
    float* out = (float*)d_out;

    cudaFuncSetAttribute(attn_kernel, cudaFuncAttributeMaxDynamicSharedMemorySize, SMEMB);
    cudaFuncSetAttribute(proj_mma, cudaFuncAttributeMaxDynamicSharedMemorySize, PJ_SMEM);

    convert_kernel<<<1044, 256>>>(x, Wq, Wk, Wv);
    proj_mma<<<dim3(96, 1, NB), 256, PJ_SMEM>>>(bq, bk, bv);
    attn_kernel<<<dim3(NN / TI, NB), 256, SMEMB>>>(x, out);
}

// round 15
// speedup vs baseline: 1.0540x; 1.0540x over previous
#include <cuda_runtime.h>
#include <cuda_fp16.h>
#include <cstdint>

#define NB 4
#define NC 256
#define NN 4096
#define TI 128
#define TJ 128
#define NSTEPS (NN / TJ)
#define TJ1 256
#define NSTEPS1 (NN / TJ1)

// ---------------- device scratch (allocation-free) ----------------
__device__ unsigned short g_q[(size_t)NB * NN * 64];     // [b][n][32hi|32lo] fp16
__device__ unsigned short g_k[(size_t)NB * NN * 64];
__device__ unsigned short g_v[(size_t)NB * NN * 256];    // [b][n][c] fp16
__device__ unsigned short g_xh[(size_t)NB * NC * NN];    // x hi plane [b][c][n]
__device__ unsigned short g_xl[(size_t)NB * NC * NN];    // x lo plane
__device__ unsigned short g_wvh[256 * 256];              // Wv hi [c][k]
__device__ unsigned short g_wvl[256 * 256];
__device__ unsigned short g_wqkh[64 * 256];              // Wq(0-31)|Wk(32-63) hi [c][k]
__device__ unsigned short g_wqkl[64 * 256];

// ---------------- attn SMEM layout (bytes) ----------------
#define SQ 0                        // 128 rows x 128B = 16384
#define SK 16384                    // + bf*16384 (128 rows x 128B), 2 bufs
#define SV 49152                    // + bf*65536 ; 128 j-rows x 512B, 2 bufs
#define SMEMB (49152 + 2 * 65536)   // 180224
// phase 1 reuses SV region: 2 x 16384 K-hi tiles

// ---------------- proj SMEM ----------------
#define PJX 0          // x tile: [2 buf][32 k][512B: 128n hi | 128n lo]
#define PJW 32768      // W tile: [2 buf][<=128 c][128B: 32k hi | 32k lo]
#define PJ_SMEM 65536

// ---------------- PTX helpers ----------------
__device__ __forceinline__ uint32_t smem_u32(const void* p) {
    uint32_t a;
    asm("{ .reg .u64 t; cvta.to.shared.u64 t, %1; cvt.u32.u64 %0, t; }" : "=r"(a) : "l"(p));
    return a;
}
__device__ __forceinline__ void cp16(uint32_t dst, const void* src) {
    asm volatile("cp.async.cg.shared.global [%0], [%1], 16;" :: "r"(dst), "l"(src));
}
__device__ __forceinline__ void cp_commit() { asm volatile("cp.async.commit_group;" ::: "memory"); }
__device__ __forceinline__ void cp_wait0()  { asm volatile("cp.async.wait_group 0;" ::: "memory"); }

__device__ __forceinline__ void ldsm4(uint32_t* r, uint32_t a) {
    asm volatile("ldmatrix.sync.aligned.m8n8.x4.shared.b16 {%0,%1,%2,%3}, [%4];"
        : "=r"(r[0]), "=r"(r[1]), "=r"(r[2]), "=r"(r[3]) : "r"(a));
}
__device__ __forceinline__ void ldsm4t(uint32_t* r, uint32_t a) {
    asm volatile("ldmatrix.sync.aligned.m8n8.x4.trans.shared.b16 {%0,%1,%2,%3}, [%4];"
        : "=r"(r[0]), "=r"(r[1]), "=r"(r[2]), "=r"(r[3]) : "r"(a));
}
__device__ __forceinline__ void mma16816(float* d, const uint32_t* a, uint32_t b0, uint32_t b1) {
    asm volatile("mma.sync.aligned.m16n8k16.row.col.f32.f16.f16.f32 "
        "{%0,%1,%2,%3}, {%4,%5,%6,%7}, {%8,%9}, {%0,%1,%2,%3};"
        : "+f"(d[0]), "+f"(d[1]), "+f"(d[2]), "+f"(d[3])
        : "r"(a[0]), "r"(a[1]), "r"(a[2]), "r"(a[3]), "r"(b0), "r"(b1));
}
// pack: first arg -> low half, second -> high half
__device__ __forceinline__ uint32_t packh(float lo, float hi) {
    uint32_t r;
    asm("cvt.rn.f16x2.f32 %0, %1, %2;" : "=r"(r) : "f"(hi), "f"(lo));
    return r;
}
__device__ __forceinline__ unsigned short f16h(float v) {
    __half h = __float2half_rn(v);
    return *reinterpret_cast<unsigned short*>(&h);
}
__device__ __forceinline__ float f16f(unsigned short u) {
    __half h = *reinterpret_cast<__half*>(&u);
    return __half2float(h);
}
__device__ __forceinline__ uint32_t swz512(int ch, int row) {
    return (uint32_t)(((ch & 24) | ((ch ^ (row & 7)) & 7)) << 4);
}
__device__ __forceinline__ void cvt4(float4 v, uint2& hh, uint2& ll) {
    uint32_t h0 = packh(v.x, v.y), h1 = packh(v.z, v.w);
    float r0 = f16f((unsigned short)(h0 & 0xffffu));
    float r1 = f16f((unsigned short)(h0 >> 16));
    float r2 = f16f((unsigned short)(h1 & 0xffffu));
    float r3 = f16f((unsigned short)(h1 >> 16));
    hh = make_uint2(h0, h1);
    ll = make_uint2(packh(v.x - r0, v.y - r1), packh(v.z - r2, v.w - r3));
}

// ---------------- attn prefetchers (256 threads) ----------------
__device__ __forceinline__ void prefetch_k256(uint32_t sb, int bf, int b, int j0, int t) {
    #pragma unroll
    for (int kk = 0; kk < 4; kk++) {
        int idx = t + kk * 256;
        int row = idx >> 2, ch = idx & 3;
        cp16(sb + SV + bf * 16384 + row * 64 + ((ch ^ ((row >> 1) & 3)) << 4),
             g_k + ((size_t)(b * NN + j0 + row)) * 64 + ch * 8);
    }
}
// full K (hi+lo, 128 rows) + V (128 j-rows x 512B)
__device__ __forceinline__ void prefetch_kv(uint32_t sb, int bf, int b, int j0, int t) {
    const unsigned short* ks = g_k + ((size_t)(b * NN + j0)) * 64;
    #pragma unroll
    for (int kk = 0; kk < 4; kk++) {
        int idx = t + kk * 256;
        int row = idx >> 3, ch = idx & 7;
        cp16(sb + SK + bf * 16384 + row * 128 + ((ch ^ (row & 7)) << 4),
             ks + (size_t)row * 64 + ch * 8);
    }
    const unsigned short* hs = g_v + ((size_t)(b * NN + j0)) * 256;
    #pragma unroll
    for (int kk = 0; kk < 16; kk++) {
        int idx = t + kk * 256;
        int row = idx >> 5, ch = idx & 31;
        uint32_t off = row * 512 + (((ch & 24) | ((ch ^ row) & 7)) << 4);
        cp16(sb + SV + bf * 65536 + off, hs + (size_t)row * 256 + ch * 8);
    }
}

// =====================================================================
// fp16 mma.sync flash attention (round-13 dataflow, TJ=128 tiles)
// =====================================================================
__global__ __launch_bounds__(256, 1) void attn_kernel(
    const float* __restrict__ x, float* __restrict__ out)
{
    extern __shared__ char smem[];
    const uint32_t sb = smem_u32(smem);
    const int t = threadIdx.x, lane = t & 31, w = t >> 5;
    const int b = blockIdx.y, i0 = blockIdx.x * TI;
    const int rr = lane >> 2, qd = lane & 3;
    const int l7 = lane & 7, lm8 = ((lane >> 3) & 1) * 8, lhi = lane >> 4, lm4 = lane >> 3;

    {
        const unsigned short* qs = g_q + ((size_t)(b * NN + i0)) * 64;
        #pragma unroll
        for (int kk = 0; kk < 4; kk++) {
            int idx = t + kk * 256;
            int row = idx >> 3, ch = idx & 7;
            cp16(sb + SQ + row * 128 + ((ch ^ (row & 7)) << 4),
                 qs + (size_t)row * 64 + ch * 8);
        }
        prefetch_k256(sb, 0, b, 0, t);
        cp_commit();
    }
    cp_wait0();
    __syncthreads();

    uint32_t qh[2][4], ql[2][4];
    #pragma unroll
    for (int kc = 0; kc < 2; kc++) {
        int row = w * 16 + l7 + lm8;
        int chh = 2 * kc + lhi;
        ldsm4(qh[kc], sb + SQ + row * 128 + ((chh ^ (row & 7)) << 4));
        ldsm4(ql[kc], sb + SQ + row * 128 + (((chh + 4) ^ (row & 7)) << 4));
    }

    // ---- PHASE 1: row max (K-hi, 256-j tiles in SV region) ----
    float mx0 = -1e30f, mx1 = -1e30f;
    for (int it = 0; it < NSTEPS1; it++) {
        const int bf = it & 1;
        if (it > 0) { cp_wait0(); __syncthreads(); }
        if (it + 1 < NSTEPS1) { prefetch_k256(sb, bf ^ 1, b, (it + 1) * TJ1, t); cp_commit(); }
        const uint32_t kb = sb + SV + bf * 16384;
        #pragma unroll
        for (int hb = 0; hb < 32; hb++) {
            float S[4] = {0.f, 0.f, 0.f, 0.f};
            int krow = hb * 8 + l7;
            uint32_t a = kb + krow * 64 + ((lm4 ^ ((krow >> 1) & 3)) << 4);
            uint32_t kh4[4];
            ldsm4(kh4, a);
            mma16816(S, qh[0], kh4[0], kh4[1]);
            mma16816(S, qh[1], kh4[2], kh4[3]);
            mx0 = fmaxf(mx0, fmaxf(S[0], S[1]));
            mx1 = fmaxf(mx1, fmaxf(S[2], S[3]));
        }
    }
    mx0 = fmaxf(mx0, __shfl_xor_sync(0xffffffffu, mx0, 1));
    mx0 = fmaxf(mx0, __shfl_xor_sync(0xffffffffu, mx0, 2));
    mx1 = fmaxf(mx1, __shfl_xor_sync(0xffffffffu, mx1, 1));
    mx1 = fmaxf(mx1, __shfl_xor_sync(0xffffffffu, mx1, 2));

    // ---- PHASE 2 ----
    float O[32][4];
    #pragma unroll
    for (int i = 0; i < 32; i++)
        #pragma unroll
        for (int j = 0; j < 4; j++) O[i][j] = 0.f;
    float rs0 = 0.f, rs1 = 0.f;

    __syncthreads();
    prefetch_kv(sb, 0, b, 0, t);
    cp_commit();
    cp_wait0();
    __syncthreads();

    for (int st = 0; st < NSTEPS; st++) {
        const int bf = st & 1;
        if (st > 0) { cp_wait0(); __syncthreads(); }
        if (st + 1 < NSTEPS) { prefetch_kv(sb, bf ^ 1, b, (st + 1) * TJ, t); cp_commit(); }

        const uint32_t kbase = sb + SK + bf * 16384;
        const uint32_t vbase = sb + SV + bf * 65536;

        #pragma unroll
        for (int kc = 0; kc < 8; kc++) {
            float S[2][4];
            #pragma unroll
            for (int h = 0; h < 2; h++) {
                S[h][0] = S[h][1] = S[h][2] = S[h][3] = 0.f;
                int krow = (2 * kc + h) * 8 + l7;
                int swk = (krow & 7);
                uint32_t kh4[4], kl4[4];
                ldsm4(kh4, kbase + krow * 128 + ((lm4 ^ swk) << 4));
                ldsm4(kl4, kbase + krow * 128 + (((lm4 + 4) ^ swk) << 4));
                mma16816(S[h], qh[0], kh4[0], kh4[1]);
                mma16816(S[h], qh[1], kh4[2], kh4[3]);
                mma16816(S[h], qh[0], kl4[0], kl4[1]);
                mma16816(S[h], qh[1], kl4[2], kl4[3]);
                mma16816(S[h], ql[0], kh4[0], kh4[1]);
                mma16816(S[h], ql[1], kh4[2], kh4[3]);
            }

            uint32_t pah[4];
            #pragma unroll
            for (int h = 0; h < 2; h++) {
                float e0 = __expf(S[h][0] - mx0), e1 = __expf(S[h][1] - mx0);
                float e2 = __expf(S[h][2] - mx1), e3 = __expf(S[h][3] - mx1);
                rs0 += e0 + e1;
                rs1 += e2 + e3;
                pah[h * 2]     = packh(e0, e1);
                pah[h * 2 + 1] = packh(e2, e3);
            }

            int vrow = kc * 16 + l7 + lm8;
            uint32_t vroff = vbase + vrow * 512;
            int swv = (vrow & 7);
            #pragma unroll
            for (int vb = 0; vb < 16; vb++) {
                int ch = vb * 2 + lhi;
                uint32_t a = vroff + ((((ch & 24) | ((ch ^ swv) & 7))) << 4);
                uint32_t vh4[4];
                ldsm4t(vh4, a);
                mma16816(O[2 * vb],     pah, vh4[0], vh4[1]);
                mma16816(O[2 * vb + 1], pah, vh4[2], vh4[3]);
            }
        }
    }

    rs0 += __shfl_xor_sync(0xffffffffu, rs0, 1);
    rs0 += __shfl_xor_sync(0xffffffffu, rs0, 2);
    rs1 += __shfl_xor_sync(0xffffffffu, rs1, 1);
    rs1 += __shfl_xor_sync(0xffffffffu, rs1, 2);
    const float li0 = 1.0f / rs0, li1 = 1.0f / rs1;

    const int ng = i0 + w * 16 + rr;
    #pragma unroll
    for (int nb = 0; nb < 32; nb++) {
        int c = nb * 8 + qd * 2;
        size_t g = ((size_t)b * NC + c) * NN + ng;
        out[g]          = O[nb][0] * li0 + x[g];
        out[g + NN]     = O[nb][1] * li0 + x[g + NN];
        out[g + 8]      = O[nb][2] * li1 + x[g + 8];
        out[g + 8 + NN] = O[nb][3] * li1 + x[g + 8 + NN];
    }
}

// =====================================================================
// convert: x -> fp16 hi/lo planes (blocks 0-1023, 4 f4/thread);
// Wv -> blocks 1024-1039; Wq -> 1040-1041; Wk -> 1042-1043.
// =====================================================================
__global__ __launch_bounds__(256) void convert_kernel(
    const float* __restrict__ x,
    const float* __restrict__ Wq, const float* __restrict__ Wk,
    const float* __restrict__ Wv)
{
    const int t = threadIdx.x;
    const int bx = blockIdx.x;
    if (bx < 1024) {
        const float4* xs = (const float4*)x;
        uint2* xh2 = (uint2*)g_xh;
        uint2* xl2 = (uint2*)g_xl;
        float4 v[4];
        size_t base = (size_t)bx * 1024 + t;
        #pragma unroll
        for (int kk = 0; kk < 4; kk++) v[kk] = xs[base + kk * 256];
        #pragma unroll
        for (int kk = 0; kk < 4; kk++) {
            uint2 hh, ll;
            cvt4(v[kk], hh, ll);
            xh2[base + kk * 256] = hh;
            xl2[base + kk * 256] = ll;
        }
    } else if (bx < 1040) {
        const float4* wv4 = (const float4*)Wv;
        uint2* vh2 = (uint2*)g_wvh;
        uint2* vl2 = (uint2*)g_wvl;
        float4 v[4];
        int base = (bx - 1024) * 1024 + t;
        #pragma unroll
        for (int kk = 0; kk < 4; kk++) v[kk] = wv4[base + kk * 256];
        #pragma unroll
        for (int kk = 0; kk < 4; kk++) {
            uint2 hh, ll;
            cvt4(v[kk], hh, ll);
            vh2[base + kk * 256] = hh;
            vl2[base + kk * 256] = ll;
        }
    } else {
        const bool isQ = bx < 1042;
        const float4* w4 = (const float4*)(isQ ? Wq : Wk);
        int base = ((bx - (isQ ? 1040 : 1042)) & 1) * 1024 + t;
        int off = isQ ? 0 : 2048;
        uint2* h2 = (uint2*)g_wqkh;
        uint2* l2 = (uint2*)g_wqkl;
        float4 v[4];
        #pragma unroll
        for (int kk = 0; kk < 4; kk++) v[kk] = w4[base + kk * 256];
        #pragma unroll
        for (int kk = 0; kk < 4; kk++) {
            uint2 hh, ll;
            cvt4(v[kk], hh, ll);
            h2[off + base + kk * 256] = hh;
            l2[off + base + kk * 256] = ll;
        }
    }
}

// =====================================================================
// proj v2: pure fp16 pipelined GEMM, D[n][c] = x^T W^T (3-product hi/lo)
// =====================================================================
template<int NU, bool ISV>
__device__ __forceinline__ void proj_body(
    char* ps, uint32_t sb, int b, int n0, int c0,
    const float* __restrict__ bq, const float* __restrict__ bk,
    const float* __restrict__ bv)
{
    const int t = threadIdx.x, lane = t & 31, w = t >> 5;
    const int rr = lane >> 2, qd = lane & 3;
    const int l7 = lane & 7, lhi = lane >> 4, lm4 = lane >> 3, lq = (lane >> 3) & 1;
    const unsigned short* wh_g = ISV ? g_wvh : g_wqkh;
    const unsigned short* wl_g = ISV ? g_wvl : g_wqkl;

    auto prefetch = [&](int bf, int k0) {
        #pragma unroll
        for (int kk = 0; kk < 4; kk++) {
            int idx = t + kk * 256;
            int row = idx >> 5, ch = idx & 31;
            const unsigned short* src = (ch < 16 ? g_xh : g_xl)
                + ((size_t)(b * NC + k0 + row)) * NN + n0 + (ch & 15) * 8;
            cp16(sb + PJX + bf * 16384 + row * 512 + swz512(ch, row), src);
        }
        #pragma unroll
        for (int kk = 0; kk < (ISV ? 4 : 2); kk++) {
            int idx = t + kk * 256;
            int row = idx >> 3, ch = idx & 7;
            const unsigned short* src = (ch < 4 ? wh_g : wl_g)
                + (size_t)(c0 + row) * 256 + k0 + (ch & 3) * 8;
            cp16(sb + PJW + bf * 16384 + row * 128 + ((ch ^ (row & 7)) << 4), src);
        }
    };

    float O[NU][4];
    #pragma unroll
    for (int i = 0; i < NU; i++)
        #pragma unroll
        for (int j = 0; j < 4; j++) O[i][j] = 0.f;

    prefetch(0, 0);
    cp_commit();

    for (int it = 0; it < 8; it++) {
        const int buf = it & 1;
        cp_wait0();
        __syncthreads();
        if (it < 7) { prefetch(buf ^ 1, (it + 1) * 32); cp_commit(); }

        uint32_t ah[2][4], al[2][4];
        #pragma unroll
        for (int kc = 0; kc < 2; kc++) {
            int krow = kc * 16 + l7 + lhi * 8;
            int chA = 2 * w + lq;
            uint32_t base = sb + PJX + buf * 16384 + krow * 512;
            ldsm4t(ah[kc], base + swz512(chA, krow));
            ldsm4t(al[kc], base + swz512(chA + 16, krow));
        }
        #pragma unroll
        for (int u = 0; u < NU; u++) {
            int crow = u * 8 + l7;
            uint32_t wb = sb + PJW + buf * 16384 + crow * 128;
            int sw = crow & 7;
            uint32_t whf[4], wlf[4];
            ldsm4(whf, wb + ((lm4 ^ sw) << 4));
            ldsm4(wlf, wb + (((lm4 + 4) ^ sw) << 4));
            mma16816(O[u], ah[0], whf[0], whf[1]);
            mma16816(O[u], ah[1], whf[2], whf[3]);
            mma16816(O[u], al[0], whf[0], whf[1]);
            mma16816(O[u], al[1], whf[2], whf[3]);
            mma16816(O[u], ah[0], wlf[0], wlf[1]);
            mma16816(O[u], ah[1], wlf[2], wlf[3]);
        }
    }

    const int n_lo = n0 + w * 16 + rr;
    if (ISV) {
        #pragma unroll
        for (int u = 0; u < NU; u++) {
            int c = c0 + u * 8 + qd * 2;
            float b0 = bv[c], b1 = bv[c + 1];
            uint32_t p0 = packh(O[u][0] + b0, O[u][1] + b1);
            uint32_t p1 = packh(O[u][2] + b0, O[u][3] + b1);
            *(uint32_t*)&g_v[((size_t)(b * NN + n_lo)) * 256 + c] = p0;
            *(uint32_t*)&g_v[((size_t)(b * NN + n_lo + 8)) * 256 + c] = p1;
        }
    } else {
        #pragma unroll
        for (int u = 0; u < NU; u++) {
            int c = u * 8 + qd * 2;
            bool isq = (c < 32);
            unsigned short* tgt = isq ? g_q : g_k;
            int cl = isq ? c : c - 32;
            const float* bb = isq ? bq : bk;
            float b0 = bb[cl], b1 = bb[cl + 1];
            #pragma unroll
            for (int hh = 0; hh < 2; hh++) {
                float v0 = O[u][2 * hh] + b0, v1 = O[u][2 * hh + 1] + b1;
                unsigned short h0 = f16h(v0), h1 = f16h(v1);
                uint32_t hp = ((uint32_t)h1 << 16) | h0;
                uint32_t lp = packh(v0 - f16f(h0), v1 - f16f(h1));
                size_t base = ((size_t)(b * NN + n_lo + hh * 8)) * 64;
                *(uint32_t*)&tgt[base + cl] = hp;
                *(uint32_t*)&tgt[base + 32 + cl] = lp;
            }
        }
    }
}

__global__ __launch_bounds__(256, 2) void proj_mma(
    const float* __restrict__ bq, const float* __restrict__ bk,
    const float* __restrict__ bv)
{
    extern __shared__ char ps[];
    const uint32_t sb = smem_u32(ps);
    const int b = blockIdx.z;
    if (blockIdx.x < 64) {
        proj_body<16, true>(ps, sb, b, (blockIdx.x >> 1) * 128,
                            (blockIdx.x & 1) * 128, bq, bk, bv);
    } else {
        proj_body<8, false>(ps, sb, b, ((int)blockIdx.x - 64) * 128, 0, bq, bk, bv);
    }
}

// =====================================================================
extern "C" void kernel_launch(void* const* d_in, const int* in_sizes, int n_in,
                              void* d_out, int out_size)
{
    const float* x  = (const float*)d_in[0];
    const float* Wq = (const float*)d_in[1];
    const float* bq = (const float*)d_in[2];
    const float* Wk = (const float*)d_in[3];
    const float* bk = (const float*)d_in[4];
    const float* Wv = (const float*)d_in[5];
    const float* bv = (const float*)d_in[6];
    float* out = (float*)d_out;

    cudaFuncSetAttribute(attn_kernel, cudaFuncAttributeMaxDynamicSharedMemorySize, SMEMB);
    cudaFuncSetAttribute(proj_mma, cudaFuncAttributeMaxDynamicSharedMemorySize, PJ_SMEM);

    convert_kernel<<<1044, 256>>>(x, Wq, Wk, Wv);
    proj_mma<<<dim3(96, 1, NB), 256, PJ_SMEM>>>(bq, bk, bv);
    attn_kernel<<<dim3(NN / TI, NB), 256, SMEMB>>>(x, out);
}

// round 16
// speedup vs baseline: 1.1762x; 1.1159x over previous
#include <cuda_runtime.h>
#include <cuda_fp16.h>
#include <cstdint>

#define NB 4
#define NC 256
#define NN 4096
#define TI 128
#define TJ 64
#define NSTEPS (NN / TJ)
#define TJ1 512
#define NSTEPS1 (NN / TJ1)

// ---------------- device scratch (allocation-free) ----------------
__device__ unsigned short g_q[(size_t)NB * NN * 64];     // [b][n][32hi|32lo] fp16
__device__ unsigned short g_k[(size_t)NB * NN * 64];
__device__ unsigned short g_v[(size_t)NB * NN * 256];    // [b][n][c] fp16
__device__ unsigned short g_xh[(size_t)NB * NC * NN];    // x hi plane [b][c][n]
__device__ unsigned short g_xl[(size_t)NB * NC * NN];    // x lo plane
__device__ unsigned short g_wvh[256 * 256];              // Wv hi [c][k]
__device__ unsigned short g_wqkh[64 * 256];              // Wq(0-31)|Wk(32-63) hi [c][k]
__device__ unsigned short g_wqkl[64 * 256];

// ---------------- attn SMEM layout (bytes) ----------------
#define SQ 0                       // 128 rows x 128B = 16384
#define SK 16384                   // + bf*8192 (64 rows x 128B)
#define SV 32768                   // + bf*32768 ; 64 j-rows x 512B
#define SMEMB (32768 + 2 * 32768)  // 98304
// phase 1 reuses SV region: 2 x 32768 K-hi tiles (512 rows x 64B)

// ---------------- proj SMEM ----------------
#define PJX 0          // x tile: [2 buf][32 k][512B: 128n hi | 128n lo]
#define PJW 32768      // W tile: [2 buf][<=128 c][128B: 32k hi | 32k lo]
#define PJ_SMEM 65536

// ---------------- PTX helpers ----------------
__device__ __forceinline__ uint32_t smem_u32(const void* p) {
    uint32_t a;
    asm("{ .reg .u64 t; cvta.to.shared.u64 t, %1; cvt.u32.u64 %0, t; }" : "=r"(a) : "l"(p));
    return a;
}
__device__ __forceinline__ void cp16(uint32_t dst, const void* src) {
    asm volatile("cp.async.cg.shared.global [%0], [%1], 16;" :: "r"(dst), "l"(src));
}
__device__ __forceinline__ void cp_commit() { asm volatile("cp.async.commit_group;" ::: "memory"); }
__device__ __forceinline__ void cp_wait0()  { asm volatile("cp.async.wait_group 0;" ::: "memory"); }

__device__ __forceinline__ void ldsm4(uint32_t* r, uint32_t a) {
    asm volatile("ldmatrix.sync.aligned.m8n8.x4.shared.b16 {%0,%1,%2,%3}, [%4];"
        : "=r"(r[0]), "=r"(r[1]), "=r"(r[2]), "=r"(r[3]) : "r"(a));
}
__device__ __forceinline__ void ldsm4t(uint32_t* r, uint32_t a) {
    asm volatile("ldmatrix.sync.aligned.m8n8.x4.trans.shared.b16 {%0,%1,%2,%3}, [%4];"
        : "=r"(r[0]), "=r"(r[1]), "=r"(r[2]), "=r"(r[3]) : "r"(a));
}
__device__ __forceinline__ void mma16816(float* d, const uint32_t* a, uint32_t b0, uint32_t b1) {
    asm volatile("mma.sync.aligned.m16n8k16.row.col.f32.f16.f16.f32 "
        "{%0,%1,%2,%3}, {%4,%5,%6,%7}, {%8,%9}, {%0,%1,%2,%3};"
        : "+f"(d[0]), "+f"(d[1]), "+f"(d[2]), "+f"(d[3])
        : "r"(a[0]), "r"(a[1]), "r"(a[2]), "r"(a[3]), "r"(b0), "r"(b1));
}
// pack: first arg -> low half, second -> high half
__device__ __forceinline__ uint32_t packh(float lo, float hi) {
    uint32_t r;
    asm("cvt.rn.f16x2.f32 %0, %1, %2;" : "=r"(r) : "f"(hi), "f"(lo));
    return r;
}
__device__ __forceinline__ unsigned short f16h(float v) {
    __half h = __float2half_rn(v);
    return *reinterpret_cast<unsigned short*>(&h);
}
__device__ __forceinline__ float f16f(unsigned short u) {
    __half h = *reinterpret_cast<__half*>(&u);
    return __half2float(h);
}
__device__ __forceinline__ uint32_t swz512(int ch, int row) {
    return (uint32_t)(((ch & 24) | ((ch ^ (row & 7)) & 7)) << 4);
}
__device__ __forceinline__ void cvt4(float4 v, uint2& hh, uint2& ll) {
    uint32_t h0 = packh(v.x, v.y), h1 = packh(v.z, v.w);
    float r0 = f16f((unsigned short)(h0 & 0xffffu));
    float r1 = f16f((unsigned short)(h0 >> 16));
    float r2 = f16f((unsigned short)(h1 & 0xffffu));
    float r3 = f16f((unsigned short)(h1 >> 16));
    hh = make_uint2(h0, h1);
    ll = make_uint2(packh(v.x - r0, v.y - r1), packh(v.z - r2, v.w - r3));
}

// ---------------- attn prefetchers (256 threads) ----------------
// phase 1: K hi-plane, 512 rows x 64B, swizzled for 64B-row ldsm
__device__ __forceinline__ void prefetch_k512(uint32_t sb, int bf, int b, int j0, int t) {
    #pragma unroll
    for (int kk = 0; kk < 8; kk++) {
        int idx = t + kk * 256;
        int row = idx >> 2, ch = idx & 3;
        cp16(sb + SV + bf * 32768 + row * 64 + ((ch ^ ((row >> 1) & 3)) << 4),
             g_k + ((size_t)(b * NN + j0 + row)) * 64 + ch * 8);
    }
}
__device__ __forceinline__ void prefetch_kv(uint32_t sb, int bf, int b, int j0, int t) {
    const unsigned short* ks = g_k + ((size_t)(b * NN + j0)) * 64;
    #pragma unroll
    for (int kk = 0; kk < 2; kk++) {
        int idx = t + kk * 256;
        int row = idx >> 3, ch = idx & 7;
        cp16(sb + SK + bf * 8192 + row * 128 + ((ch ^ (row & 7)) << 4),
             ks + (size_t)row * 64 + ch * 8);
    }
    const unsigned short* hs = g_v + ((size_t)(b * NN + j0)) * 256;
    #pragma unroll
    for (int kk = 0; kk < 8; kk++) {
        int idx = t + kk * 256;
        int row = idx >> 5, ch = idx & 31;
        uint32_t off = row * 512 + (((ch & 24) | ((ch ^ row) & 7)) << 4);
        cp16(sb + SV + bf * 32768 + off, hs + (size_t)row * 256 + ch * 8);
    }
}

// =====================================================================
// fp16 mma.sync flash attention (round-13 dataflow; phase-1 TJ1=512)
// =====================================================================
__global__ __launch_bounds__(256, 1) void attn_kernel(
    const float* __restrict__ x, float* __restrict__ out)
{
    extern __shared__ char smem[];
    const uint32_t sb = smem_u32(smem);
    const int t = threadIdx.x, lane = t & 31, w = t >> 5;
    const int b = blockIdx.y, i0 = blockIdx.x * TI;
    const int rr = lane >> 2, qd = lane & 3;
    const int l7 = lane & 7, lm8 = ((lane >> 3) & 1) * 8, lhi = lane >> 4, lm4 = lane >> 3;

    {
        const unsigned short* qs = g_q + ((size_t)(b * NN + i0)) * 64;
        #pragma unroll
        for (int kk = 0; kk < 4; kk++) {
            int idx = t + kk * 256;
            int row = idx >> 3, ch = idx & 7;
            cp16(sb + SQ + row * 128 + ((ch ^ (row & 7)) << 4),
                 qs + (size_t)row * 64 + ch * 8);
        }
        prefetch_k512(sb, 0, b, 0, t);
        cp_commit();
    }
    cp_wait0();
    __syncthreads();

    uint32_t qh[2][4], ql[2][4];
    #pragma unroll
    for (int kc = 0; kc < 2; kc++) {
        int row = w * 16 + l7 + lm8;
        int chh = 2 * kc + lhi;
        ldsm4(qh[kc], sb + SQ + row * 128 + ((chh ^ (row & 7)) << 4));
        ldsm4(ql[kc], sb + SQ + row * 128 + (((chh + 4) ^ (row & 7)) << 4));
    }

    // ---- PHASE 1: row max (8 tiles of 512 j) ----
    float mx0 = -1e30f, mx1 = -1e30f;
    for (int it = 0; it < NSTEPS1; it++) {
        const int bf = it & 1;
        if (it > 0) { cp_wait0(); __syncthreads(); }
        if (it + 1 < NSTEPS1) { prefetch_k512(sb, bf ^ 1, b, (it + 1) * TJ1, t); cp_commit(); }
        const uint32_t kb = sb + SV + bf * 32768;
        #pragma unroll
        for (int hb = 0; hb < 64; hb++) {
            float S[4] = {0.f, 0.f, 0.f, 0.f};
            int krow = hb * 8 + l7;
            uint32_t a = kb + krow * 64 + ((lm4 ^ ((krow >> 1) & 3)) << 4);
            uint32_t kh4[4];
            ldsm4(kh4, a);
            mma16816(S, qh[0], kh4[0], kh4[1]);
            mma16816(S, qh[1], kh4[2], kh4[3]);
            mx0 = fmaxf(mx0, fmaxf(S[0], S[1]));
            mx1 = fmaxf(mx1, fmaxf(S[2], S[3]));
        }
    }
    mx0 = fmaxf(mx0, __shfl_xor_sync(0xffffffffu, mx0, 1));
    mx0 = fmaxf(mx0, __shfl_xor_sync(0xffffffffu, mx0, 2));
    mx1 = fmaxf(mx1, __shfl_xor_sync(0xffffffffu, mx1, 1));
    mx1 = fmaxf(mx1, __shfl_xor_sync(0xffffffffu, mx1, 2));

    // ---- PHASE 2 ----
    float O[32][4];
    #pragma unroll
    for (int i = 0; i < 32; i++)
        #pragma unroll
        for (int j = 0; j < 4; j++) O[i][j] = 0.f;
    float rs0 = 0.f, rs1 = 0.f;

    __syncthreads();
    prefetch_kv(sb, 0, b, 0, t);
    cp_commit();
    cp_wait0();
    __syncthreads();

    for (int st = 0; st < NSTEPS; st++) {
        const int bf = st & 1;
        if (st > 0) { cp_wait0(); __syncthreads(); }
        if (st + 1 < NSTEPS) { prefetch_kv(sb, bf ^ 1, b, (st + 1) * TJ, t); cp_commit(); }

        const uint32_t kbase = sb + SK + bf * 8192;
        const uint32_t vbase = sb + SV + bf * 32768;

        #pragma unroll
        for (int kc = 0; kc < 4; kc++) {
            float S[2][4];
            #pragma unroll
            for (int h = 0; h < 2; h++) {
                S[h][0] = S[h][1] = S[h][2] = S[h][3] = 0.f;
                int krow = (2 * kc + h) * 8 + l7;
                int swk = (krow & 7);
                uint32_t kh4[4], kl4[4];
                ldsm4(kh4, kbase + krow * 128 + ((lm4 ^ swk) << 4));
                ldsm4(kl4, kbase + krow * 128 + (((lm4 + 4) ^ swk) << 4));
                mma16816(S[h], qh[0], kh4[0], kh4[1]);
                mma16816(S[h], qh[1], kh4[2], kh4[3]);
                mma16816(S[h], qh[0], kl4[0], kl4[1]);
                mma16816(S[h], qh[1], kl4[2], kl4[3]);
                mma16816(S[h], ql[0], kh4[0], kh4[1]);
                mma16816(S[h], ql[1], kh4[2], kh4[3]);
            }

            uint32_t pah[4];
            #pragma unroll
            for (int h = 0; h < 2; h++) {
                float e0 = __expf(S[h][0] - mx0), e1 = __expf(S[h][1] - mx0);
                float e2 = __expf(S[h][2] - mx1), e3 = __expf(S[h][3] - mx1);
                rs0 += e0 + e1;
                rs1 += e2 + e3;
                pah[h * 2]     = packh(e0, e1);
                pah[h * 2 + 1] = packh(e2, e3);
            }

            int vrow = kc * 16 + l7 + lm8;
            uint32_t vroff = vbase + vrow * 512;
            int swv = (vrow & 7);
            #pragma unroll
            for (int vb = 0; vb < 16; vb++) {
                int ch = vb * 2 + lhi;
                uint32_t a = vroff + ((((ch & 24) | ((ch ^ swv) & 7))) << 4);
                uint32_t vh4[4];
                ldsm4t(vh4, a);
                mma16816(O[2 * vb],     pah, vh4[0], vh4[1]);
                mma16816(O[2 * vb + 1], pah, vh4[2], vh4[3]);
            }
        }
    }

    rs0 += __shfl_xor_sync(0xffffffffu, rs0, 1);
    rs0 += __shfl_xor_sync(0xffffffffu, rs0, 2);
    rs1 += __shfl_xor_sync(0xffffffffu, rs1, 1);
    rs1 += __shfl_xor_sync(0xffffffffu, rs1, 2);
    const float li0 = 1.0f / rs0, li1 = 1.0f / rs1;

    const int ng = i0 + w * 16 + rr;
    #pragma unroll
    for (int nb = 0; nb < 32; nb++) {
        int c = nb * 8 + qd * 2;
        size_t g = ((size_t)b * NC + c) * NN + ng;
        out[g]          = O[nb][0] * li0 + x[g];
        out[g + NN]     = O[nb][1] * li0 + x[g + NN];
        out[g + 8]      = O[nb][2] * li1 + x[g + 8];
        out[g + 8 + NN] = O[nb][3] * li1 + x[g + 8 + NN];
    }
}

// =====================================================================
// convert: x -> fp16 hi/lo planes (blocks 0-1023, 4 f4/thread);
// Wv(hi only) -> blocks 1024-1039; Wq -> 1040-1041; Wk -> 1042-1043.
// =====================================================================
__global__ __launch_bounds__(256) void convert_kernel(
    const float* __restrict__ x,
    const float* __restrict__ Wq, const float* __restrict__ Wk,
    const float* __restrict__ Wv)
{
    const int t = threadIdx.x;
    const int bx = blockIdx.x;
    if (bx < 1024) {
        const float4* xs = (const float4*)x;
        uint2* xh2 = (uint2*)g_xh;
        uint2* xl2 = (uint2*)g_xl;
        float4 v[4];
        size_t base = (size_t)bx * 1024 + t;
        #pragma unroll
        for (int kk = 0; kk < 4; kk++) v[kk] = xs[base + kk * 256];
        #pragma unroll
        for (int kk = 0; kk < 4; kk++) {
            uint2 hh, ll;
            cvt4(v[kk], hh, ll);
            xh2[base + kk * 256] = hh;
            xl2[base + kk * 256] = ll;
        }
    } else if (bx < 1040) {
        const float4* wv4 = (const float4*)Wv;
        uint2* vh2 = (uint2*)g_wvh;
        float4 v[4];
        int base = (bx - 1024) * 1024 + t;
        #pragma unroll
        for (int kk = 0; kk < 4; kk++) v[kk] = wv4[base + kk * 256];
        #pragma unroll
        for (int kk = 0; kk < 4; kk++) {
            uint2 hh, ll;
            cvt4(v[kk], hh, ll);
            vh2[base + kk * 256] = hh;
        }
    } else {
        const bool isQ = bx < 1042;
        const float4* w4 = (const float4*)(isQ ? Wq : Wk);
        int base = ((bx - (isQ ? 1040 : 1042)) & 1) * 1024 + t;
        int off = isQ ? 0 : 2048;
        uint2* h2 = (uint2*)g_wqkh;
        uint2* l2 = (uint2*)g_wqkl;
        float4 v[4];
        #pragma unroll
        for (int kk = 0; kk < 4; kk++) v[kk] = w4[base + kk * 256];
        #pragma unroll
        for (int kk = 0; kk < 4; kk++) {
            uint2 hh, ll;
            cvt4(v[kk], hh, ll);
            h2[off + base + kk * 256] = hh;
            l2[off + base + kk * 256] = ll;
        }
    }
}

// =====================================================================
// proj v2: pure fp16 pipelined GEMM, D[n][c] = x^T W^T
// V path: 2-product (x hi+lo, W hi only). QK path: 3-product.
// =====================================================================
template<int NU, bool ISV>
__device__ __forceinline__ void proj_body(
    char* ps, uint32_t sb, int b, int n0, int c0,
    const float* __restrict__ bq, const float* __restrict__ bk,
    const float* __restrict__ bv)
{
    const int t = threadIdx.x, lane = t & 31, w = t >> 5;
    const int rr = lane >> 2, qd = lane & 3;
    const int l7 = lane & 7, lhi = lane >> 4, lm4 = lane >> 3, lq = (lane >> 3) & 1;

    auto prefetch = [&](int bf, int k0) {
        #pragma unroll
        for (int kk = 0; kk < 4; kk++) {
            int idx = t + kk * 256;
            int row = idx >> 5, ch = idx & 31;
            const unsigned short* src = (ch < 16 ? g_xh : g_xl)
                + ((size_t)(b * NC + k0 + row)) * NN + n0 + (ch & 15) * 8;
            cp16(sb + PJX + bf * 16384 + row * 512 + swz512(ch, row), src);
        }
        if (ISV) {
            // W hi only: 128 rows x 4 chunks
            #pragma unroll
            for (int kk = 0; kk < 2; kk++) {
                int idx = t + kk * 256;
                int row = idx >> 2, ch = idx & 3;
                const unsigned short* src = g_wvh
                    + (size_t)(c0 + row) * 256 + k0 + ch * 8;
                cp16(sb + PJW + bf * 16384 + row * 128 + ((ch ^ (row & 7)) << 4), src);
            }
        } else {
            // W hi+lo: 64 rows x 8 chunks
            #pragma unroll
            for (int kk = 0; kk < 2; kk++) {
                int idx = t + kk * 256;
                int row = idx >> 3, ch = idx & 7;
                const unsigned short* src = (ch < 4 ? g_wqkh : g_wqkl)
                    + (size_t)(c0 + row) * 256 + k0 + (ch & 3) * 8;
                cp16(sb + PJW + bf * 16384 + row * 128 + ((ch ^ (row & 7)) << 4), src);
            }
        }
    };

    float O[NU][4];
    #pragma unroll
    for (int i = 0; i < NU; i++)
        #pragma unroll
        for (int j = 0; j < 4; j++) O[i][j] = 0.f;

    prefetch(0, 0);
    cp_commit();

    for (int it = 0; it < 8; it++) {
        const int buf = it & 1;
        cp_wait0();
        __syncthreads();
        if (it < 7) { prefetch(buf ^ 1, (it + 1) * 32); cp_commit(); }

        uint32_t ah[2][4], al[2][4];
        #pragma unroll
        for (int kc = 0; kc < 2; kc++) {
            int krow = kc * 16 + l7 + lhi * 8;
            int chA = 2 * w + lq;
            uint32_t base = sb + PJX + buf * 16384 + krow * 512;
            ldsm4t(ah[kc], base + swz512(chA, krow));
            ldsm4t(al[kc], base + swz512(chA + 16, krow));
        }
        #pragma unroll
        for (int u = 0; u < NU; u++) {
            int crow = u * 8 + l7;
            uint32_t wb = sb + PJW + buf * 16384 + crow * 128;
            int sw = crow & 7;
            uint32_t whf[4];
            ldsm4(whf, wb + ((lm4 ^ sw) << 4));
            mma16816(O[u], ah[0], whf[0], whf[1]);
            mma16816(O[u], ah[1], whf[2], whf[3]);
            mma16816(O[u], al[0], whf[0], whf[1]);
            mma16816(O[u], al[1], whf[2], whf[3]);
            if (!ISV) {
                uint32_t wlf[4];
                ldsm4(wlf, wb + (((lm4 + 4) ^ sw) << 4));
                mma16816(O[u], ah[0], wlf[0], wlf[1]);
                mma16816(O[u], ah[1], wlf[2], wlf[3]);
            }
        }
    }

    const int n_lo = n0 + w * 16 + rr;
    if (ISV) {
        #pragma unroll
        for (int u = 0; u < NU; u++) {
            int c = c0 + u * 8 + qd * 2;
            float b0 = bv[c], b1 = bv[c + 1];
            uint32_t p0 = packh(O[u][0] + b0, O[u][1] + b1);
            uint32_t p1 = packh(O[u][2] + b0, O[u][3] + b1);
            *(uint32_t*)&g_v[((size_t)(b * NN + n_lo)) * 256 + c] = p0;
            *(uint32_t*)&g_v[((size_t)(b * NN + n_lo + 8)) * 256 + c] = p1;
        }
    } else {
        #pragma unroll
        for (int u = 0; u < NU; u++) {
            int c = u * 8 + qd * 2;
            bool isq = (c < 32);
            unsigned short* tgt = isq ? g_q : g_k;
            int cl = isq ? c : c - 32;
            const float* bb = isq ? bq : bk;
            float b0 = bb[cl], b1 = bb[cl + 1];
            #pragma unroll
            for (int hh = 0; hh < 2; hh++) {
                float v0 = O[u][2 * hh] + b0, v1 = O[u][2 * hh + 1] + b1;
                unsigned short h0 = f16h(v0), h1 = f16h(v1);
                uint32_t hp = ((uint32_t)h1 << 16) | h0;
                uint32_t lp = packh(v0 - f16f(h0), v1 - f16f(h1));
                size_t base = ((size_t)(b * NN + n_lo + hh * 8)) * 64;
                *(uint32_t*)&tgt[base + cl] = hp;
                *(uint32_t*)&tgt[base + 32 + cl] = lp;
            }
        }
    }
}

__global__ __launch_bounds__(256, 2) void proj_mma(
    const float* __restrict__ bq, const float* __restrict__ bk,
    const float* __restrict__ bv)
{
    extern __shared__ char ps[];
    const uint32_t sb = smem_u32(ps);
    const int b = blockIdx.z;
    if (blockIdx.x < 64) {
        proj_body<16, true>(ps, sb, b, (blockIdx.x >> 1) * 128,
                            (blockIdx.x & 1) * 128, bq, bk, bv);
    } else {
        proj_body<8, false>(ps, sb, b, ((int)blockIdx.x - 64) * 128, 0, bq, bk, bv);
    }
}

// =====================================================================
extern "C" void kernel_launch(void* const* d_in, const int* in_sizes, int n_in,
                              void* d_out, int out_size)
{
    const float* x  = (const float*)d_in[0];
    const float* Wq = (const float*)d_in[1];
    const float* bq = (const float*)d_in[2];
    const float* Wk = (const float*)d_in[3];
    const float* bk = (const float*)d_in[4];
    const float* Wv = (const float*)d_in[5];
    const float* bv = (const float*)d_in[6];
    float* out = (float*)d_out;

    cudaFuncSetAttribute(attn_kernel, cudaFuncAttributeMaxDynamicSharedMemorySize, SMEMB);
    cudaFuncSetAttribute(proj_mma, cudaFuncAttributeMaxDynamicSharedMemorySize, PJ_SMEM);

    convert_kernel<<<1044, 256>>>(x, Wq, Wk, Wv);
    proj_mma<<<dim3(96, 1, NB), 256, PJ_SMEM>>>(bq, bk, bv);
    attn_kernel<<<dim3(NN / TI, NB), 256, SMEMB>>>(x, out);
}

// round 17
// speedup vs baseline: 1.1830x; 1.0058x over previous
#include <cuda_runtime.h>
#include <cuda_fp16.h>
#include <cstdint>

#define NB 4
#define NC 256
#define NN 4096
#define TI 128
#define TJ 64
#define NSTEPS (NN / TJ)
#define TJ1 512
#define NSTEPS1 (NN / TJ1)

// ---------------- device scratch (allocation-free) ----------------
__device__ unsigned short g_q[(size_t)NB * NN * 64];     // [b][n][32hi|32lo] fp16
__device__ unsigned short g_k[(size_t)NB * NN * 64];
__device__ unsigned short g_v[(size_t)NB * NN * 256];    // [b][n][c] fp16
__device__ unsigned short g_xh[(size_t)NB * NC * NN];    // x hi plane [b][c][n]
__device__ unsigned short g_xl[(size_t)NB * NC * NN];    // x lo plane
__device__ unsigned short g_wvh[256 * 256];              // Wv hi [c][k]
__device__ unsigned short g_wqkh[64 * 256];              // Wq(0-31)|Wk(32-63) hi [c][k]
__device__ unsigned short g_wqkl[64 * 256];

// ---------------- attn SMEM layout (bytes) ----------------
#define SQ 0                       // 128 rows x 128B = 16384
#define SK 16384                   // + bf*8192 (64 rows x 128B)
#define SV 32768                   // + bf*32768 ; 64 j-rows x 512B
#define SMEMB (32768 + 2 * 32768)  // 98304
// phase 1 reuses SV region: 2 x 32768 K-hi tiles (512 rows x 64B)

// ---------------- proj SMEM ----------------
#define PJX 0          // x tile: [2 buf][32 k][512B: 128n hi | 128n lo]
#define PJW 32768      // W tile: [2 buf][<=128 c][128B]
#define PJ_SMEM 65536

// ---------------- PTX helpers ----------------
__device__ __forceinline__ uint32_t smem_u32(const void* p) {
    uint32_t a;
    asm("{ .reg .u64 t; cvta.to.shared.u64 t, %1; cvt.u32.u64 %0, t; }" : "=r"(a) : "l"(p));
    return a;
}
__device__ __forceinline__ void cp16(uint32_t dst, const void* src) {
    asm volatile("cp.async.cg.shared.global [%0], [%1], 16;" :: "r"(dst), "l"(src));
}
__device__ __forceinline__ void cp_commit() { asm volatile("cp.async.commit_group;" ::: "memory"); }
__device__ __forceinline__ void cp_wait0()  { asm volatile("cp.async.wait_group 0;" ::: "memory"); }

__device__ __forceinline__ void ldsm4(uint32_t* r, uint32_t a) {
    asm volatile("ldmatrix.sync.aligned.m8n8.x4.shared.b16 {%0,%1,%2,%3}, [%4];"
        : "=r"(r[0]), "=r"(r[1]), "=r"(r[2]), "=r"(r[3]) : "r"(a));
}
__device__ __forceinline__ void ldsm4t(uint32_t* r, uint32_t a) {
    asm volatile("ldmatrix.sync.aligned.m8n8.x4.trans.shared.b16 {%0,%1,%2,%3}, [%4];"
        : "=r"(r[0]), "=r"(r[1]), "=r"(r[2]), "=r"(r[3]) : "r"(a));
}
__device__ __forceinline__ void mma16816(float* d, const uint32_t* a, uint32_t b0, uint32_t b1) {
    asm volatile("mma.sync.aligned.m16n8k16.row.col.f32.f16.f16.f32 "
        "{%0,%1,%2,%3}, {%4,%5,%6,%7}, {%8,%9}, {%0,%1,%2,%3};"
        : "+f"(d[0]), "+f"(d[1]), "+f"(d[2]), "+f"(d[3])
        : "r"(a[0]), "r"(a[1]), "r"(a[2]), "r"(a[3]), "r"(b0), "r"(b1));
}
// pack: first arg -> low half, second -> high half
__device__ __forceinline__ uint32_t packh(float lo, float hi) {
    uint32_t r;
    asm("cvt.rn.f16x2.f32 %0, %1, %2;" : "=r"(r) : "f"(hi), "f"(lo));
    return r;
}
__device__ __forceinline__ unsigned short f16h(float v) {
    __half h = __float2half_rn(v);
    return *reinterpret_cast<unsigned short*>(&h);
}
__device__ __forceinline__ float f16f(unsigned short u) {
    __half h = *reinterpret_cast<__half*>(&u);
    return __half2float(h);
}
__device__ __forceinline__ uint32_t swz512(int ch, int row) {
    return (uint32_t)(((ch & 24) | ((ch ^ (row & 7)) & 7)) << 4);
}
__device__ __forceinline__ void cvt4(float4 v, uint2& hh, uint2& ll) {
    uint32_t h0 = packh(v.x, v.y), h1 = packh(v.z, v.w);
    float r0 = f16f((unsigned short)(h0 & 0xffffu));
    float r1 = f16f((unsigned short)(h0 >> 16));
    float r2 = f16f((unsigned short)(h1 & 0xffffu));
    float r3 = f16f((unsigned short)(h1 >> 16));
    hh = make_uint2(h0, h1);
    ll = make_uint2(packh(v.x - r0, v.y - r1), packh(v.z - r2, v.w - r3));
}

// ---------------- attn prefetchers (256 threads) ----------------
// phase 1: K hi-plane, 512 rows x 64B, swizzled for 64B-row ldsm
__device__ __forceinline__ void prefetch_k512(uint32_t sb, int bf, int b, int j0, int t) {
    #pragma unroll
    for (int kk = 0; kk < 8; kk++) {
        int idx = t + kk * 256;
        int row = idx >> 2, ch = idx & 3;
        cp16(sb + SV + bf * 32768 + row * 64 + ((ch ^ ((row >> 1) & 3)) << 4),
             g_k + ((size_t)(b * NN + j0 + row)) * 64 + ch * 8);
    }
}
__device__ __forceinline__ void prefetch_kv(uint32_t sb, int bf, int b, int j0, int t) {
    const unsigned short* ks = g_k + ((size_t)(b * NN + j0)) * 64;
    #pragma unroll
    for (int kk = 0; kk < 2; kk++) {
        int idx = t + kk * 256;
        int row = idx >> 3, ch = idx & 7;
        cp16(sb + SK + bf * 8192 + row * 128 + ((ch ^ (row & 7)) << 4),
             ks + (size_t)row * 64 + ch * 8);
    }
    const unsigned short* hs = g_v + ((size_t)(b * NN + j0)) * 256;
    #pragma unroll
    for (int kk = 0; kk < 8; kk++) {
        int idx = t + kk * 256;
        int row = idx >> 5, ch = idx & 31;
        uint32_t off = row * 512 + (((ch & 24) | ((ch ^ row) & 7)) << 4);
        cp16(sb + SV + bf * 32768 + off, hs + (size_t)row * 256 + ch * 8);
    }
}

// =====================================================================
// fp16 mma.sync flash attention (round-13 dataflow; phase-1 TJ1=512)
// =====================================================================
__global__ __launch_bounds__(256, 1) void attn_kernel(
    const float* __restrict__ x, float* __restrict__ out)
{
    extern __shared__ char smem[];
    const uint32_t sb = smem_u32(smem);
    const int t = threadIdx.x, lane = t & 31, w = t >> 5;
    const int b = blockIdx.y, i0 = blockIdx.x * TI;
    const int rr = lane >> 2, qd = lane & 3;
    const int l7 = lane & 7, lm8 = ((lane >> 3) & 1) * 8, lhi = lane >> 4, lm4 = lane >> 3;

    {
        const unsigned short* qs = g_q + ((size_t)(b * NN + i0)) * 64;
        #pragma unroll
        for (int kk = 0; kk < 4; kk++) {
            int idx = t + kk * 256;
            int row = idx >> 3, ch = idx & 7;
            cp16(sb + SQ + row * 128 + ((ch ^ (row & 7)) << 4),
                 qs + (size_t)row * 64 + ch * 8);
        }
        prefetch_k512(sb, 0, b, 0, t);
        cp_commit();
    }
    cp_wait0();
    __syncthreads();

    uint32_t qh[2][4], ql[2][4];
    #pragma unroll
    for (int kc = 0; kc < 2; kc++) {
        int row = w * 16 + l7 + lm8;
        int chh = 2 * kc + lhi;
        ldsm4(qh[kc], sb + SQ + row * 128 + ((chh ^ (row & 7)) << 4));
        ldsm4(ql[kc], sb + SQ + row * 128 + (((chh + 4) ^ (row & 7)) << 4));
    }

    // ---- PHASE 1: row max (8 tiles of 512 j) ----
    float mx0 = -1e30f, mx1 = -1e30f;
    for (int it = 0; it < NSTEPS1; it++) {
        const int bf = it & 1;
        if (it > 0) { cp_wait0(); __syncthreads(); }
        if (it + 1 < NSTEPS1) { prefetch_k512(sb, bf ^ 1, b, (it + 1) * TJ1, t); cp_commit(); }
        const uint32_t kb = sb + SV + bf * 32768;
        #pragma unroll
        for (int hb = 0; hb < 64; hb++) {
            float S[4] = {0.f, 0.f, 0.f, 0.f};
            int krow = hb * 8 + l7;
            uint32_t a = kb + krow * 64 + ((lm4 ^ ((krow >> 1) & 3)) << 4);
            uint32_t kh4[4];
            ldsm4(kh4, a);
            mma16816(S, qh[0], kh4[0], kh4[1]);
            mma16816(S, qh[1], kh4[2], kh4[3]);
            mx0 = fmaxf(mx0, fmaxf(S[0], S[1]));
            mx1 = fmaxf(mx1, fmaxf(S[2], S[3]));
        }
    }
    mx0 = fmaxf(mx0, __shfl_xor_sync(0xffffffffu, mx0, 1));
    mx0 = fmaxf(mx0, __shfl_xor_sync(0xffffffffu, mx0, 2));
    mx1 = fmaxf(mx1, __shfl_xor_sync(0xffffffffu, mx1, 1));
    mx1 = fmaxf(mx1, __shfl_xor_sync(0xffffffffu, mx1, 2));

    // ---- PHASE 2 ----
    float O[32][4];
    #pragma unroll
    for (int i = 0; i < 32; i++)
        #pragma unroll
        for (int j = 0; j < 4; j++) O[i][j] = 0.f;
    float rs0 = 0.f, rs1 = 0.f;

    __syncthreads();
    prefetch_kv(sb, 0, b, 0, t);
    cp_commit();
    cp_wait0();
    __syncthreads();

    for (int st = 0; st < NSTEPS; st++) {
        const int bf = st & 1;
        if (st > 0) { cp_wait0(); __syncthreads(); }
        if (st + 1 < NSTEPS) { prefetch_kv(sb, bf ^ 1, b, (st + 1) * TJ, t); cp_commit(); }

        const uint32_t kbase = sb + SK + bf * 8192;
        const uint32_t vbase = sb + SV + bf * 32768;

        #pragma unroll
        for (int kc = 0; kc < 4; kc++) {
            float S[2][4];
            #pragma unroll
            for (int h = 0; h < 2; h++) {
                S[h][0] = S[h][1] = S[h][2] = S[h][3] = 0.f;
                int krow = (2 * kc + h) * 8 + l7;
                int swk = (krow & 7);
                uint32_t kh4[4], kl4[4];
                ldsm4(kh4, kbase + krow * 128 + ((lm4 ^ swk) << 4));
                ldsm4(kl4, kbase + krow * 128 + (((lm4 + 4) ^ swk) << 4));
                mma16816(S[h], qh[0], kh4[0], kh4[1]);
                mma16816(S[h], qh[1], kh4[2], kh4[3]);
                mma16816(S[h], qh[0], kl4[0], kl4[1]);
                mma16816(S[h], qh[1], kl4[2], kl4[3]);
                mma16816(S[h], ql[0], kh4[0], kh4[1]);
                mma16816(S[h], ql[1], kh4[2], kh4[3]);
            }

            uint32_t pah[4];
            #pragma unroll
            for (int h = 0; h < 2; h++) {
                float e0 = __expf(S[h][0] - mx0), e1 = __expf(S[h][1] - mx0);
                float e2 = __expf(S[h][2] - mx1), e3 = __expf(S[h][3] - mx1);
                rs0 += e0 + e1;
                rs1 += e2 + e3;
                pah[h * 2]     = packh(e0, e1);
                pah[h * 2 + 1] = packh(e2, e3);
            }

            int vrow = kc * 16 + l7 + lm8;
            uint32_t vroff = vbase + vrow * 512;
            int swv = (vrow & 7);
            #pragma unroll
            for (int vb = 0; vb < 16; vb++) {
                int ch = vb * 2 + lhi;
                uint32_t a = vroff + ((((ch & 24) | ((ch ^ swv) & 7))) << 4);
                uint32_t vh4[4];
                ldsm4t(vh4, a);
                mma16816(O[2 * vb],     pah, vh4[0], vh4[1]);
                mma16816(O[2 * vb + 1], pah, vh4[2], vh4[3]);
            }
        }
    }

    rs0 += __shfl_xor_sync(0xffffffffu, rs0, 1);
    rs0 += __shfl_xor_sync(0xffffffffu, rs0, 2);
    rs1 += __shfl_xor_sync(0xffffffffu, rs1, 1);
    rs1 += __shfl_xor_sync(0xffffffffu, rs1, 2);
    const float li0 = 1.0f / rs0, li1 = 1.0f / rs1;

    const int ng = i0 + w * 16 + rr;
    #pragma unroll
    for (int nb = 0; nb < 32; nb++) {
        int c = nb * 8 + qd * 2;
        size_t g = ((size_t)b * NC + c) * NN + ng;
        out[g]          = O[nb][0] * li0 + x[g];
        out[g + NN]     = O[nb][1] * li0 + x[g + NN];
        out[g + 8]      = O[nb][2] * li1 + x[g + 8];
        out[g + 8 + NN] = O[nb][3] * li1 + x[g + 8 + NN];
    }
}

// =====================================================================
// convert: x -> fp16 hi/lo planes (blocks 0-1023, 4 f4/thread);
// Wv(hi only) -> blocks 1024-1039; Wq -> 1040-1041; Wk -> 1042-1043.
// =====================================================================
__global__ __launch_bounds__(256) void convert_kernel(
    const float* __restrict__ x,
    const float* __restrict__ Wq, const float* __restrict__ Wk,
    const float* __restrict__ Wv)
{
    const int t = threadIdx.x;
    const int bx = blockIdx.x;
    if (bx < 1024) {
        const float4* xs = (const float4*)x;
        uint2* xh2 = (uint2*)g_xh;
        uint2* xl2 = (uint2*)g_xl;
        float4 v[4];
        size_t base = (size_t)bx * 1024 + t;
        #pragma unroll
        for (int kk = 0; kk < 4; kk++) v[kk] = xs[base + kk * 256];
        #pragma unroll
        for (int kk = 0; kk < 4; kk++) {
            uint2 hh, ll;
            cvt4(v[kk], hh, ll);
            xh2[base + kk * 256] = hh;
            xl2[base + kk * 256] = ll;
        }
    } else if (bx < 1040) {
        const float4* wv4 = (const float4*)Wv;
        uint2* vh2 = (uint2*)g_wvh;
        float4 v[4];
        int base = (bx - 1024) * 1024 + t;
        #pragma unroll
        for (int kk = 0; kk < 4; kk++) v[kk] = wv4[base + kk * 256];
        #pragma unroll
        for (int kk = 0; kk < 4; kk++) {
            uint2 hh, ll;
            cvt4(v[kk], hh, ll);
            vh2[base + kk * 256] = hh;
        }
    } else {
        const bool isQ = bx < 1042;
        const float4* w4 = (const float4*)(isQ ? Wq : Wk);
        int base = ((bx - (isQ ? 1040 : 1042)) & 1) * 1024 + t;
        int off = isQ ? 0 : 2048;
        uint2* h2 = (uint2*)g_wqkh;
        uint2* l2 = (uint2*)g_wqkl;
        float4 v[4];
        #pragma unroll
        for (int kk = 0; kk < 4; kk++) v[kk] = w4[base + kk * 256];
        #pragma unroll
        for (int kk = 0; kk < 4; kk++) {
            uint2 hh, ll;
            cvt4(v[kk], hh, ll);
            h2[off + base + kk * 256] = hh;
            l2[off + base + kk * 256] = ll;
        }
    }
}

// =====================================================================
// proj v2: pure fp16 pipelined GEMM, D[n][c] = x^T W^T
// V path: 1-product (x hi, W hi). QK path: 3-product (hi/lo).
// =====================================================================
template<int NU, bool ISV>
__device__ __forceinline__ void proj_body(
    char* ps, uint32_t sb, int b, int n0, int c0,
    const float* __restrict__ bq, const float* __restrict__ bk,
    const float* __restrict__ bv)
{
    const int t = threadIdx.x, lane = t & 31, w = t >> 5;
    const int rr = lane >> 2, qd = lane & 3;
    const int l7 = lane & 7, lhi = lane >> 4, lm4 = lane >> 3, lq = (lane >> 3) & 1;

    auto prefetch = [&](int bf, int k0) {
        if (ISV) {
            // x hi only: 32 rows x 16 chunks
            #pragma unroll
            for (int kk = 0; kk < 2; kk++) {
                int idx = t + kk * 256;
                int row = idx >> 4, ch = idx & 15;
                const unsigned short* src = g_xh
                    + ((size_t)(b * NC + k0 + row)) * NN + n0 + ch * 8;
                cp16(sb + PJX + bf * 16384 + row * 512 + swz512(ch, row), src);
            }
            // W hi only: 128 rows x 4 chunks
            #pragma unroll
            for (int kk = 0; kk < 2; kk++) {
                int idx = t + kk * 256;
                int row = idx >> 2, ch = idx & 3;
                const unsigned short* src = g_wvh
                    + (size_t)(c0 + row) * 256 + k0 + ch * 8;
                cp16(sb + PJW + bf * 16384 + row * 128 + ((ch ^ (row & 7)) << 4), src);
            }
        } else {
            // x hi+lo: 32 rows x 32 chunks
            #pragma unroll
            for (int kk = 0; kk < 4; kk++) {
                int idx = t + kk * 256;
                int row = idx >> 5, ch = idx & 31;
                const unsigned short* src = (ch < 16 ? g_xh : g_xl)
                    + ((size_t)(b * NC + k0 + row)) * NN + n0 + (ch & 15) * 8;
                cp16(sb + PJX + bf * 16384 + row * 512 + swz512(ch, row), src);
            }
            // W hi+lo: 64 rows x 8 chunks
            #pragma unroll
            for (int kk = 0; kk < 2; kk++) {
                int idx = t + kk * 256;
                int row = idx >> 3, ch = idx & 7;
                const unsigned short* src = (ch < 4 ? g_wqkh : g_wqkl)
                    + (size_t)(c0 + row) * 256 + k0 + (ch & 3) * 8;
                cp16(sb + PJW + bf * 16384 + row * 128 + ((ch ^ (row & 7)) << 4), src);
            }
        }
    };

    float O[NU][4];
    #pragma unroll
    for (int i = 0; i < NU; i++)
        #pragma unroll
        for (int j = 0; j < 4; j++) O[i][j] = 0.f;

    prefetch(0, 0);
    cp_commit();

    for (int it = 0; it < 8; it++) {
        const int buf = it & 1;
        cp_wait0();
        __syncthreads();
        if (it < 7) { prefetch(buf ^ 1, (it + 1) * 32); cp_commit(); }

        uint32_t ah[2][4], al[2][4];
        #pragma unroll
        for (int kc = 0; kc < 2; kc++) {
            int krow = kc * 16 + l7 + lhi * 8;
            int chA = 2 * w + lq;
            uint32_t base = sb + PJX + buf * 16384 + krow * 512;
            ldsm4t(ah[kc], base + swz512(chA, krow));
            if (!ISV) ldsm4t(al[kc], base + swz512(chA + 16, krow));
        }
        #pragma unroll
        for (int u = 0; u < NU; u++) {
            int crow = u * 8 + l7;
            uint32_t wb = sb + PJW + buf * 16384 + crow * 128;
            int sw = crow & 7;
            uint32_t whf[4];
            ldsm4(whf, wb + ((lm4 ^ sw) << 4));
            mma16816(O[u], ah[0], whf[0], whf[1]);
            mma16816(O[u], ah[1], whf[2], whf[3]);
            if (!ISV) {
                mma16816(O[u], al[0], whf[0], whf[1]);
                mma16816(O[u], al[1], whf[2], whf[3]);
                uint32_t wlf[4];
                ldsm4(wlf, wb + (((lm4 + 4) ^ sw) << 4));
                mma16816(O[u], ah[0], wlf[0], wlf[1]);
                mma16816(O[u], ah[1], wlf[2], wlf[3]);
            }
        }
    }

    const int n_lo = n0 + w * 16 + rr;
    if (ISV) {
        #pragma unroll
        for (int u = 0; u < NU; u++) {
            int c = c0 + u * 8 + qd * 2;
            float b0 = bv[c], b1 = bv[c + 1];
            uint32_t p0 = packh(O[u][0] + b0, O[u][1] + b1);
            uint32_t p1 = packh(O[u][2] + b0, O[u][3] + b1);
            *(uint32_t*)&g_v[((size_t)(b * NN + n_lo)) * 256 + c] = p0;
            *(uint32_t*)&g_v[((size_t)(b * NN + n_lo + 8)) * 256 + c] = p1;
        }
    } else {
        #pragma unroll
        for (int u = 0; u < NU; u++) {
            int c = u * 8 + qd * 2;
            bool isq = (c < 32);
            unsigned short* tgt = isq ? g_q : g_k;
            int cl = isq ? c : c - 32;
            const float* bb = isq ? bq : bk;
            float b0 = bb[cl], b1 = bb[cl + 1];
            #pragma unroll
            for (int hh = 0; hh < 2; hh++) {
                float v0 = O[u][2 * hh] + b0, v1 = O[u][2 * hh + 1] + b1;
                unsigned short h0 = f16h(v0), h1 = f16h(v1);
                uint32_t hp = ((uint32_t)h1 << 16) | h0;
                uint32_t lp = packh(v0 - f16f(h0), v1 - f16f(h1));
                size_t base = ((size_t)(b * NN + n_lo + hh * 8)) * 64;
                *(uint32_t*)&tgt[base + cl] = hp;
                *(uint32_t*)&tgt[base + 32 + cl] = lp;
            }
        }
    }
}

__global__ __launch_bounds__(256, 2) void proj_mma(
    const float* __restrict__ bq, const float* __restrict__ bk,
    const float* __restrict__ bv)
{
    extern __shared__ char ps[];
    const uint32_t sb = smem_u32(ps);
    const int b = blockIdx.z;
    if (blockIdx.x < 64) {
        proj_body<16, true>(ps, sb, b, (blockIdx.x >> 1) * 128,
                            (blockIdx.x & 1) * 128, bq, bk, bv);
    } else {
        proj_body<8, false>(ps, sb, b, ((int)blockIdx.x - 64) * 128, 0, bq, bk, bv);
    }
}

// =====================================================================
extern "C" void kernel_launch(void* const* d_in, const int* in_sizes, int n_in,
                              void* d_out, int out_size)
{
    const float* x  = (const float*)d_in[0];
    const float* Wq = (const float*)d_in[1];
    const float* bq = (const float*)d_in[2];
    const float* Wk = (const float*)d_in[3];
    const float* bk = (const float*)d_in[4];
    const float* Wv = (const float*)d_in[5];
    const float* bv = (const float*)d_in[6];
    float* out = (float*)d_out;

    cudaFuncSetAttribute(attn_kernel, cudaFuncAttributeMaxDynamicSharedMemorySize, SMEMB);
    cudaFuncSetAttribute(proj_mma, cudaFuncAttributeMaxDynamicSharedMemorySize, PJ_SMEM);

    convert_kernel<<<1044, 256>>>(x, Wq, Wk, Wv);
    proj_mma<<<dim3(96, 1, NB), 256, PJ_SMEM>>>(bq, bk, bv);
    attn_kernel<<<dim3(NN / TI, NB), 256, SMEMB>>>(x, out);
}